// round 2
// baseline (speedup 1.0000x reference)
#include <cuda_runtime.h>

// LearnableWaveletTransform: depthwise 1D cross-correlation, 2 shared 96-tap
// filters over x[64,128,4096] fp32, pad=48 -> out (l,h) each [64,128,4097].
//
// Strategy: compute-bound on FMA pipe. Use fma.rn.f32x2 packing the TWO
// FILTERS into the two f32 lanes (w_pair = (l_w[k], h_w[k])), halving FMA
// instruction count. Sliding register window of duplicated x pairs; full
// unroll so rotation is register renaming (no MOVs).

#define KW      96
#define PADW    48
#define TLEN    4096
#define TOUT    4097
#define NROWS   8192            // 64 * 128
#define TILE    2048
#define RPT     8               // outputs per thread
#define NTHREADS 256
#define WINLEN  (TILE + KW)     // 2144
#define HALFOFF ((long long)NROWS * (long long)TOUT)  // 33,562,624

__device__ __forceinline__ unsigned long long ffma2(unsigned long long a,
                                                    unsigned long long b,
                                                    unsigned long long c) {
    unsigned long long d;
    asm("fma.rn.f32x2 %0, %1, %2, %3;" : "=l"(d) : "l"(a), "l"(b), "l"(c));
    return d;
}
__device__ __forceinline__ unsigned long long pack2(float lo, float hi) {
    unsigned long long r;
    asm("mov.b64 %0, {%1, %2};" : "=l"(r) : "f"(lo), "f"(hi));
    return r;
}
__device__ __forceinline__ void unpack2(unsigned long long v, float& lo, float& hi) {
    asm("mov.b64 {%0, %1}, %2;" : "=f"(lo), "=f"(hi) : "l"(v));
}

__global__ void __launch_bounds__(NTHREADS)
wavelet_f32x2_kernel(const float* __restrict__ x,
                     const float* __restrict__ hw,
                     const float* __restrict__ lw,
                     float* __restrict__ out)
{
    __shared__ float sx[WINLEN];
    __shared__ unsigned long long wp[KW];

    const int row  = blockIdx.y;
    const int tile = blockIdx.x;
    const int tid  = threadIdx.x;

    const int t_base = tile * TILE;
    const long long xbase = (long long)row * TLEN;
    const int g0 = t_base - PADW;   // global x index of window element 0

    // Cooperative window load (zero-padded at row boundaries)
    for (int i = tid; i < WINLEN; i += NTHREADS) {
        int g = g0 + i;
        sx[i] = (g >= 0 && g < TLEN) ? x[xbase + g] : 0.0f;
    }
    // Pack filters: lane.lo = l_w, lane.hi = h_w
    if (tid < KW) wp[tid] = pack2(lw[tid], hw[tid]);
    __syncthreads();

    const int t0 = t_base + tid * RPT;
    if (t0 < TOUT) {
        const int s0 = tid * RPT;

        // Sliding window of duplicated-pair x values
        unsigned long long xd[RPT];
        #pragma unroll
        for (int j = 0; j < RPT; ++j) {
            float v = sx[s0 + j];
            xd[j] = pack2(v, v);
        }

        unsigned long long acc[RPT];
        #pragma unroll
        for (int j = 0; j < RPT; ++j) acc[j] = 0ULL;   // (+0.0f, +0.0f)

        #pragma unroll
        for (int k = 0; k < KW; ++k) {
            unsigned long long w = wp[k];              // ld.shared.b64 broadcast
            #pragma unroll
            for (int j = 0; j < RPT; ++j)
                acc[j] = ffma2(xd[j], w, acc[j]);
            // shift window left by one, bring in next x (in-bounds: max idx 2143)
            #pragma unroll
            for (int j = 0; j < RPT - 1; ++j) xd[j] = xd[j + 1];
            float v = sx[s0 + RPT + k];
            xd[RPT - 1] = pack2(v, v);
        }

        const long long obase = (long long)row * TOUT;
        #pragma unroll
        for (int j = 0; j < RPT; ++j) {
            int t = t0 + j;
            if (t < TOUT) {
                float lo, hi;
                unpack2(acc[j], lo, hi);
                out[obase + t]           = lo;   // l_outs first
                out[HALFOFF + obase + t] = hi;   // h_outs second
            }
        }
    }
}

extern "C" void kernel_launch(void* const* d_in, const int* in_sizes, int n_in,
                              void* d_out, int out_size) {
    // metadata order: x, h_w, l_w ; output: (l_outs, h_outs) concatenated
    const float* x  = (const float*)d_in[0];
    const float* hw = (const float*)d_in[1];
    const float* lw = (const float*)d_in[2];
    float* out = (float*)d_out;

    dim3 grid(3, NROWS);   // ceil(4097 / 2048) = 3 tiles per row
    dim3 block(NTHREADS);
    wavelet_f32x2_kernel<<<grid, block>>>(x, hw, lw, out);
}